// round 13
// baseline (speedup 1.0000x reference)
#include <cuda_runtime.h>

#define NGRID   41088
#define PMAX    404
#define MDIM    192
#define KR      192
#define KF      96
#define BCN     1024
#define TWO_PI_F 6.28318530717958647692f

typedef unsigned long long u64;
typedef unsigned int u32;

// Pre-folded stage-A output: (re,im) pairs, layout [m][kf][bc], kf in [0,96)
__device__ u64 g_rip[(size_t)MDIM * KF * BCN];   // A+ = A[k] + A[191-k]
__device__ u64 g_rim[(size_t)MDIM * KF * BCN];   // A- = A[k] - A[191-k]
// Stage-B staging: (re,im) pairs, layout [m][l][bc]
__device__ u64 g_st[(size_t)MDIM * MDIM * BCN];

__device__ __forceinline__ u64 ffma2(u64 a, u64 b, u64 c) {
    u64 d; asm("fma.rn.f32x2 %0,%1,%2,%3;" : "=l"(d) : "l"(a), "l"(b), "l"(c)); return d;
}
__device__ __forceinline__ u64 fmul2(u64 a, u64 b) {
    u64 d; asm("mul.rn.f32x2 %0,%1,%2;" : "=l"(d) : "l"(a), "l"(b)); return d;
}
__device__ __forceinline__ u64 fadd2(u64 a, u64 b) {
    u64 d; asm("add.rn.f32x2 %0,%1,%2;" : "=l"(d) : "l"(a), "l"(b)); return d;
}
__device__ __forceinline__ u64 pk2(float lo, float hi) {
    u64 r; asm("mov.b64 %0,{%1,%2};" : "=l"(r) : "f"(lo), "f"(hi)); return r;
}
__device__ __forceinline__ void lds2(u64& a, u64& b, u32 addr) {
    asm volatile("ld.shared.v2.u64 {%0,%1},[%2];" : "=l"(a), "=l"(b) : "r"(addr));
}
__device__ __forceinline__ float4 lds4f(u32 addr) {
    float4 v;
    asm volatile("ld.shared.v4.f32 {%0,%1,%2,%3},[%4];"
                 : "=f"(v.x), "=f"(v.y), "=f"(v.z), "=f"(v.w) : "r"(addr));
    return v;
}
__device__ __forceinline__ void sts4(u32 addr, float a, float b, float c, float d) {
    asm volatile("st.shared.v4.f32 [%0],{%1,%2,%3,%4};" :: "r"(addr), "f"(a), "f"(b), "f"(c), "f"(d));
}
__device__ __forceinline__ void sts2(u32 addr, float a, float b) {
    asm volatile("st.shared.v2.f32 [%0],{%1,%2};" :: "r"(addr), "f"(a), "f"(b));
}
__device__ __forceinline__ void sts1(u32 addr, float a) {
    asm volatile("st.shared.f32 [%0],%1;" :: "r"(addr), "f"(a));
}
__device__ __forceinline__ u32 s2u(const void* p) {
    u32 a; asm("{.reg .u64 t; cvta.to.shared.u64 t,%1; cvt.u32.u64 %0,t;}" : "=r"(a) : "l"(p)); return a;
}
__device__ __forceinline__ void cpa16(u32 dst, const void* src, int bytes) {
    asm volatile("cp.async.cg.shared.global [%0],[%1],16,%2;" :: "r"(dst), "l"(src), "r"(bytes));
}
__device__ __forceinline__ void cpcommit() { asm volatile("cp.async.commit_group;"); }
__device__ __forceinline__ void cpwait0()  { asm volatile("cp.async.wait_group 0;"); }

// ---------------------------------------------------------------------------
// Stage A: folded per-ring DFT on ring PAIRS (k1, 191-k1).
// grid = (32 bc-tiles of 32, 96 pairs big-first, 3 m-tiles of 64), 256 thr.
// Occupancy-oriented: thread tile 4m x 2bc x 2rings (16 acc = 32 regs),
// target 3 blocks/SM (24 warps) to cover LDS/LDG/barrier latency that round-12
// profiling showed as the binder (occ 24.6%, issue 36%, fma 45%).
// Warp (mw = w&3, bw = w>>2) owns 16m x 16bc x 2rings.
// Lane (lm = lane>>3, lb = lane&7): m = mw*16+lm*4+j, bc = bw*16 + 2lb {+0,+1}.
// smem: CS[buf][16q][64 m u64] row 512B | XS[buf][16q][2 ring][32 bc u64] row 512B.
// ---------------------------------------------------------------------------
extern "C" __global__ void __launch_bounds__(256, 3)
sht_stageA(const float* __restrict__ x,
           const float* __restrict__ cosb,
           const float* __restrict__ sinb)
{
    __shared__ __align__(16) unsigned char sm[2 * 16 * 512 + 2 * 16 * 512]; // 32768
    const int t   = threadIdx.x;
    const int bc0 = blockIdx.x * 32;
    const int k1  = 95 - blockIdx.y;        // big rings first (k1=95: nlon 404)
    const int m0  = blockIdx.z * 64;

    const int nlon  = 24 + 4 * k1;
    const int slon1 = 2 * k1 * k1 + 22 * k1;
    const int q2    = k1 + 1;               // = 192 - k2, k2 = 96 + blockIdx.y
    const int slon2 = NGRID - (2 * q2 * q2 + 22 * q2);
    int mmax = 12 + 2 * k1;
    if (mmax > MDIM - 1) mmax = MDIM - 1;   // identical for both rings of pair
    if (m0 > mmax) return;                  // inactive m-tile: never read downstream
    const int half   = nlon >> 1;
    const int ntiles = (half + 16) >> 4;    // ceil((half+1)/16)

    const u32 sb = s2u(sm);
    const u32 CS = sb;                      // [buf][16q][64 m u64], row 512 B
    const u32 XS = sb + 16384;              // [buf][16q][2 ring][32 bc u64], row 512 B

    // staging roles
    const int ppb = t >> 4, mq = (t & 15) * 4;   // basis: 1 q-row, 4 m
    const int bcr = t >> 2, pq = (t & 3) * 4;    // x: 1 (ring,bc)-row, 4 q
    const int ring = bcr >> 5, bcl = bcr & 31;

    // compute roles: warp (mw, bw); lane (lm, lb)
    const int w = t >> 5, lane = t & 31;
    const int mw = w & 3, bw = w >> 2;
    const int lm = lane >> 3, lb = lane & 7;

    const float* xrow  = x + (size_t)(bc0 + bcl) * NGRID + (ring ? slon2 : slon1);
    const float* cbase = cosb + ((size_t)k1 * PMAX) * MDIM + m0 + mq;
    const float* sbase = sinb + ((size_t)k1 * PMAX) * MDIM + m0 + mq;

    u64 acc0[4][2], acc1[4][2];
#pragma unroll
    for (int j = 0; j < 4; j++)
#pragma unroll
        for (int i = 0; i < 2; i++) { acc0[j][i] = 0ull; acc1[j][i] = 0ull; }

    float4 c4, s4, fw0, bw0;
    float ps0;
    int p0s;
    const float4 z4 = make_float4(0.f, 0.f, 0.f, 0.f);

    auto prefetch = [&](int p0) {
        p0s = p0;
        int p = p0 + ppb;                   // p <= 207 < PMAX: in-bounds
        c4 = *(const float4*)(cbase + (size_t)p * MDIM);
        s4 = *(const float4*)(sbase + (size_t)p * MDIM);
        int q0 = p0 + pq;
        if (q0 <= half) {
            fw0 = *(const float4*)(xrow + q0);
            bw0 = *(const float4*)(xrow + nlon - q0 - 4);
            ps0 = (q0 >= 1) ? xrow[nlon - q0] : 0.f;
        } else { fw0 = z4; bw0 = z4; ps0 = 0.f; }
    };

    auto store_tile = [&](int buf) {
        u32 cs = CS + buf * 8192 + ppb * 512 + mq * 8;
        sts4(cs,      c4.x, s4.x, c4.y, s4.y);
        sts4(cs + 16, c4.z, s4.z, c4.w, s4.w);
        // fold + emit 4 q-rows
        u32 xa = XS + buf * 8192 + pq * 512 + ring * 256 + bcl * 8;
        const float fr[4] = {fw0.x, fw0.y, fw0.z, fw0.w};
        const float pr[4] = {ps0, bw0.w, bw0.z, bw0.y};
        int q0 = p0s + pq;
#pragma unroll
        for (int i = 0; i < 4; i++) {
            int q = q0 + i;
            bool valid = q <= half;
            bool spec  = (q == 0) || (q == half);
            float pl = valid ? (spec ? fr[i] : fr[i] + pr[i]) : 0.f;
            float mi = (valid && !spec) ? fr[i] - pr[i] : 0.f;
            sts2(xa + i * 512, pl, mi);
        }
    };

    auto compute = [&](int buf) {
        u32 cs = CS + buf * 8192 + mw * 128 + lm * 32;
        u32 xs = XS + buf * 8192 + bw * 128 + lb * 16;
#pragma unroll
        for (int pp = 0; pp < 16; ++pp) {
            u64 b0, b1, b2, b3;
            lds2(b0, b1, cs + pp * 512);
            lds2(b2, b3, cs + pp * 512 + 16);
            u64 v0, v1, u0, u1;
            lds2(v0, v1, xs + pp * 512);          // ring0 bc bw16+{2lb,2lb+1}
            lds2(u0, u1, xs + pp * 512 + 256);    // ring1 bc bw16+{2lb,2lb+1}
            acc0[0][0] = ffma2(b0, v0, acc0[0][0]);
            acc0[0][1] = ffma2(b0, v1, acc0[0][1]);
            acc0[1][0] = ffma2(b1, v0, acc0[1][0]);
            acc0[1][1] = ffma2(b1, v1, acc0[1][1]);
            acc0[2][0] = ffma2(b2, v0, acc0[2][0]);
            acc0[2][1] = ffma2(b2, v1, acc0[2][1]);
            acc0[3][0] = ffma2(b3, v0, acc0[3][0]);
            acc0[3][1] = ffma2(b3, v1, acc0[3][1]);
            acc1[0][0] = ffma2(b0, u0, acc1[0][0]);
            acc1[0][1] = ffma2(b0, u1, acc1[0][1]);
            acc1[1][0] = ffma2(b1, u0, acc1[1][0]);
            acc1[1][1] = ffma2(b1, u1, acc1[1][1]);
            acc1[2][0] = ffma2(b2, u0, acc1[2][0]);
            acc1[2][1] = ffma2(b2, u1, acc1[2][1]);
            acc1[3][0] = ffma2(b3, u0, acc1[3][0]);
            acc1[3][1] = ffma2(b3, u1, acc1[3][1]);
        }
    };

    prefetch(0);
    store_tile(0);
    __syncthreads();
    for (int ti = 0; ti < ntiles; ++ti) {
        bool nx = (ti + 1) < ntiles;
        if (nx) prefetch((ti + 1) << 4);
        compute(ti & 1);
        if (nx) store_tile((ti + 1) & 1);
        __syncthreads();
    }

    // epilogue: fold across hemisphere pair, scale by 2*pi, STG.128.
    // thread bc = bw*16 + 2lb {+0,+1}; m = m0 + mw*16 + lm*4 + j.
    const u64 tp2  = pk2(TWO_PI_F, TWO_PI_F);
    const u64 NEG1 = pk2(-1.f, -1.f);
#pragma unroll
    for (int j = 0; j < 4; j++) {
        size_t base = ((size_t)(m0 + mw * 16 + lm * 4 + j) * KF + k1) * BCN
                      + bc0 + bw * 16 + 2 * lb;
        ulonglong2 wp, wm;
        wp.x = fmul2(fadd2(acc0[j][0], acc1[j][0]), tp2);
        wp.y = fmul2(fadd2(acc0[j][1], acc1[j][1]), tp2);
        wm.x = fmul2(ffma2(acc1[j][0], NEG1, acc0[j][0]), tp2);
        wm.y = fmul2(ffma2(acc1[j][1], NEG1, acc0[j][1]), tp2);
        *(ulonglong2*)(g_rip + base) = wp;
        *(ulonglong2*)(g_rim + base) = wm;
    }
}

// ---------------------------------------------------------------------------
// Stage B: per-m GEMM on pre-folded operands, parity-coherent warps.
//   weight[m,l,k] = (-1)^(l+m) weight[m,l,191-k]
//   st[m,l,bc] = sum_{k in [klo,95]} W[m,l,k] * ( (l+m) even ? A+[k] : A-[k] )
// grid = (16 bc-tiles of 64, 3 l-tiles of 64, 192 m), block = 128.
// ---------------------------------------------------------------------------
extern "C" __global__ void __launch_bounds__(128, 4)
sht_stageB(const float* __restrict__ weight)
{
    __shared__ __align__(16) unsigned char sm[4 * 16 * 512 + 2 * 16 * 256];  // 40960
    const int t   = threadIdx.x;
    const int bc0 = blockIdx.x * 64;
    const int l0  = blockIdx.y * 64;
    const int m   = blockIdx.z;
    if (l0 + 63 < m) return;                // zero triangle: handled by transpose

    const int klo = (m <= 12) ? 0 : ((m - 11) >> 1);   // klo <= 90 < 96
    const int kb0 = klo & ~15;
    const int nkt = ((95 - kb0) >> 4) + 1;  // tiles cover [kb0, 95] exactly

    const u32 sb  = s2u(sm);
    const u32 APS = sb;                     // A+ : [buf][16k][64bc u64], row 512 B
    const u32 AMS = sb + 16384;             // A-
    const u32 WS  = sb + 32768;             // W  : [buf][16k][2 par][32 lc] f32, row 256 B

    // staging roles
    const int lr = t >> 1, kq = (t & 1) * 8;       // W: 1 l-row, 8 k
    const int wpar = (lr + m) & 1, wlc = lr >> 1;

    // compute roles
    const int w = t >> 5, lane = t & 31;
    const int pw  = w & 1;                  // warp parity: 0 -> A+, 1 -> A-
    const int h   = w >> 1;                 // bc half
    const int lc0 = (lane >> 3) * 8;        // 8 consecutive compacted l
    const int bto = h * 32 + (lane & 7) * 4;
    const int dlt = pw ^ (m & 1);           // actual l = l0 + 2*lc + dlt

    const float* wrow   = weight + ((size_t)m * MDIM + l0 + lr) * KR;
    const u64*   apbase = g_rip + ((size_t)m * KF) * BCN + bc0;
    const u64*   ambase = g_rim + ((size_t)m * KF) * BCN + bc0;

    u64 acc[8][4];
#pragma unroll
    for (int j = 0; j < 8; j++)
#pragma unroll
        for (int i = 0; i < 4; i++) acc[j][i] = 0ull;

    float4 w40, w41;
    auto cpa_tile = [&](int buf, int kb) {
#pragma unroll
        for (int c = 0; c < 4; c++) {
            int chunk = t * 4 + c;          // 0..511
            int kk = chunk >> 5, col = chunk & 31;
            int kg = kb + kk;               // kg <= 95 always
            int bytes = (kg >= klo) ? 16 : 0;   // zero-fill below band
            cpa16(APS + buf * 8192 + kk * 512 + col * 16,
                  apbase + (size_t)kg * BCN + col * 2, bytes);
            cpa16(AMS + buf * 8192 + kk * 512 + col * 16,
                  ambase + (size_t)kg * BCN + col * 2, bytes);
        }
        cpcommit();
    };
    auto ldW = [&](int kb) {
        w40 = *(const float4*)(wrow + kb + kq);
        w41 = *(const float4*)(wrow + kb + kq + 4);
    };
    auto stW = [&](int buf) {
        u32 ws = WS + buf * 4096 + wpar * 128 + wlc * 4;
        sts1(ws + (kq + 0) * 256, w40.x);
        sts1(ws + (kq + 1) * 256, w40.y);
        sts1(ws + (kq + 2) * 256, w40.z);
        sts1(ws + (kq + 3) * 256, w40.w);
        sts1(ws + (kq + 4) * 256, w41.x);
        sts1(ws + (kq + 5) * 256, w41.y);
        sts1(ws + (kq + 6) * 256, w41.z);
        sts1(ws + (kq + 7) * 256, w41.w);
    };

    const u32 AT = pw ? AMS : APS;

    auto compute = [&](int buf) {
        u32 as_ = AT + buf * 8192 + bto * 8;
        u32 ws  = WS + buf * 4096 + pw * 128 + lc0 * 4;
#pragma unroll
        for (int kk = 0; kk < 16; ++kk) {
            u64 a[4];
            lds2(a[0], a[1], as_ + kk * 512);
            lds2(a[2], a[3], as_ + kk * 512 + 16);
            float4 f0 = lds4f(ws + kk * 256);
            float4 f1 = lds4f(ws + kk * 256 + 16);
            const float fw[8] = {f0.x, f0.y, f0.z, f0.w, f1.x, f1.y, f1.z, f1.w};
#pragma unroll
            for (int j = 0; j < 8; j++) {
                u64 ww = pk2(fw[j], fw[j]);
#pragma unroll
                for (int i = 0; i < 4; i++)
                    acc[j][i] = ffma2(a[i], ww, acc[j][i]);
            }
        }
    };

    cpa_tile(0, kb0);
    ldW(kb0);
    stW(0);
    cpwait0();
    __syncthreads();
    for (int ti = 0; ti < nkt; ++ti) {
        int kb = kb0 + ((ti + 1) << 4);
        bool nx = (ti + 1) < nkt;
        if (nx) { cpa_tile((ti + 1) & 1, kb); ldW(kb); }
        compute(ti & 1);
        if (nx) { stW((ti + 1) & 1); cpwait0(); }
        __syncthreads();
    }

    // coalesced staging writes: [m][l][bc]; rows l = l0 + 2*(lc0+j) + dlt
#pragma unroll
    for (int j = 0; j < 8; j++) {
        int l = l0 + 2 * (lc0 + j) + dlt;
        u64* o = g_st + (((size_t)m * MDIM) + l) * BCN + bc0 + bto;
        ulonglong2 w0, w1;
        w0.x = acc[j][0]; w0.y = acc[j][1];
        w1.x = acc[j][2]; w1.y = acc[j][3];
        *(ulonglong2*)o       = w0;
        *(ulonglong2*)(o + 2) = w1;
    }
}

// ---------------------------------------------------------------------------
// Transpose: out[bc][l][m] <- g_st[m][l][bc]; zero for l < m.
// grid = (16 bc-tiles of 64, 6 m-tiles of 32, 192 l), block = 256.
// ---------------------------------------------------------------------------
extern "C" __global__ void __launch_bounds__(256)
sht_transpose(u64* __restrict__ out)
{
    __shared__ u64 smt[32][65];
    const int t   = threadIdx.x;
    const int bc0 = blockIdx.x * 64;
    const int m0  = blockIdx.y * 32;
    const int l   = blockIdx.z;

    const int mr  = t >> 5;            // 0..7
    const int bcc = (t & 31) * 2;      // 0..62
#pragma unroll
    for (int r = 0; r < 4; ++r) {
        int ml = mr + r * 8;
        ulonglong2 v;
        if (l >= m0 + ml)
            v = *(const ulonglong2*)(g_st + (((size_t)(m0 + ml)) * MDIM + l) * BCN + bc0 + bcc);
        else
            v = make_ulonglong2(0ull, 0ull);
        smt[ml][bcc]     = v.x;
        smt[ml][bcc + 1] = v.y;
    }
    __syncthreads();

    const int bcr = t >> 4;            // 0..15
    const int mc  = (t & 15) * 2;      // 0..30
#pragma unroll
    for (int r = 0; r < 4; ++r) {
        int bcl = bcr + r * 16;
        ulonglong2 v;
        v.x = smt[mc][bcl];
        v.y = smt[mc + 1][bcl];
        *(ulonglong2*)(out + (((size_t)(bc0 + bcl)) * MDIM + l) * MDIM + m0 + mc) = v;
    }
}

// ---------------------------------------------------------------------------

extern "C" void kernel_launch(void* const* d_in, const int* in_sizes, int n_in,
                              void* d_out, int out_size)
{
    (void)in_sizes; (void)n_in; (void)out_size;
    const float* x      = (const float*)d_in[0];
    const float* weight = (const float*)d_in[1];
    const float* cosb   = (const float*)d_in[2];
    const float* sinb   = (const float*)d_in[3];

    dim3 gA(32, 96, 3);
    sht_stageA<<<gA, 256>>>(x, cosb, sinb);

    dim3 gB(16, 3, 192);
    sht_stageB<<<gB, 128>>>(weight);

    dim3 gT(16, 6, 192);
    sht_transpose<<<gT, 256>>>((u64*)d_out);
}

// round 14
// speedup vs baseline: 1.1229x; 1.1229x over previous
#include <cuda_runtime.h>

#define NGRID   41088
#define PMAX    404
#define MDIM    192
#define KR      192
#define KF      96
#define BCN     1024
#define TWO_PI_F 6.28318530717958647692f

typedef unsigned long long u64;
typedef unsigned int u32;

// Pre-folded stage-A output: (re,im) pairs, layout [m][kf][bc], kf in [0,96)
__device__ u64 g_rip[(size_t)MDIM * KF * BCN];   // A+ = A[k] + A[191-k]
__device__ u64 g_rim[(size_t)MDIM * KF * BCN];   // A- = A[k] - A[191-k]
// Stage-B staging: (re,im) pairs, layout [m][l][bc]
__device__ u64 g_st[(size_t)MDIM * MDIM * BCN];

__device__ __forceinline__ u64 ffma2(u64 a, u64 b, u64 c) {
    u64 d; asm("fma.rn.f32x2 %0,%1,%2,%3;" : "=l"(d) : "l"(a), "l"(b), "l"(c)); return d;
}
__device__ __forceinline__ u64 fmul2(u64 a, u64 b) {
    u64 d; asm("mul.rn.f32x2 %0,%1,%2;" : "=l"(d) : "l"(a), "l"(b)); return d;
}
__device__ __forceinline__ u64 fadd2(u64 a, u64 b) {
    u64 d; asm("add.rn.f32x2 %0,%1,%2;" : "=l"(d) : "l"(a), "l"(b)); return d;
}
__device__ __forceinline__ u64 pk2(float lo, float hi) {
    u64 r; asm("mov.b64 %0,{%1,%2};" : "=l"(r) : "f"(lo), "f"(hi)); return r;
}
__device__ __forceinline__ void lds2(u64& a, u64& b, u32 addr) {
    asm volatile("ld.shared.v2.u64 {%0,%1},[%2];" : "=l"(a), "=l"(b) : "r"(addr));
}
__device__ __forceinline__ float4 lds4f(u32 addr) {
    float4 v;
    asm volatile("ld.shared.v4.f32 {%0,%1,%2,%3},[%4];"
                 : "=f"(v.x), "=f"(v.y), "=f"(v.z), "=f"(v.w) : "r"(addr));
    return v;
}
__device__ __forceinline__ void sts4(u32 addr, float a, float b, float c, float d) {
    asm volatile("st.shared.v4.f32 [%0],{%1,%2,%3,%4};" :: "r"(addr), "f"(a), "f"(b), "f"(c), "f"(d));
}
__device__ __forceinline__ void sts2(u32 addr, float a, float b) {
    asm volatile("st.shared.v2.f32 [%0],{%1,%2};" :: "r"(addr), "f"(a), "f"(b));
}
__device__ __forceinline__ void sts1(u32 addr, float a) {
    asm volatile("st.shared.f32 [%0],%1;" :: "r"(addr), "f"(a));
}
__device__ __forceinline__ u32 s2u(const void* p) {
    u32 a; asm("{.reg .u64 t; cvta.to.shared.u64 t,%1; cvt.u32.u64 %0,t;}" : "=r"(a) : "l"(p)); return a;
}
__device__ __forceinline__ void cpa16(u32 dst, const void* src, int bytes) {
    asm volatile("cp.async.cg.shared.global [%0],[%1],16,%2;" :: "r"(dst), "l"(src), "r"(bytes));
}
__device__ __forceinline__ void cpcommit() { asm volatile("cp.async.commit_group;"); }
__device__ __forceinline__ void cpwait0()  { asm volatile("cp.async.wait_group 0;"); }

// ---------------------------------------------------------------------------
// Stage A: DOUBLE-folded per-ring DFT on ring PAIRS (k1, 191-k1).
// Fold 1 (hermitian): xp[q]=x[q]+x[n-q], xm[q]=x[q]-x[n-q], q in [0, half].
// Fold 2 (q -> half-q): c[half-q,m]=(-1)^m c[q,m], s[half-q,m]=-(-1)^m s[q,m]:
//   even m: re uses XA=xp[q]+xp[half-q], im uses XB=xm[q]-xm[half-q]
//   odd  m: re uses XC=xp[q]-xp[half-q], im uses XD=xm[q]+xm[half-q]
//   q in [0, h2], h2 = half/2. Edges: q=0 pairs with q=half; q=h2 self (once).
// Warps parity-specialized: warp (par, mch, bw) owns 16 compacted-m of one
// parity x 32 bc x 2 rings; thread 4m x 4bc x 2rings = 32 FFMA2 / q-step with
// the same 6 lds2/step as round 11 -- but HALF the q range.
// grid = (16 bc-tiles of 64, 96 pairs big-first, 3 m-tiles of 64), 256 thr.
// smem (dynamic, 80KB): CS[2][16q][2par][32mc u64] rows 512B
//                       XS[2][16q][2par][2ring][64bc u64] rows 2048B
// ---------------------------------------------------------------------------
extern "C" __global__ void __launch_bounds__(256, 2)
sht_stageA(const float* __restrict__ x,
           const float* __restrict__ cosb,
           const float* __restrict__ sinb)
{
    extern __shared__ __align__(16) unsigned char smA[];   // 81920 B
    const int t   = threadIdx.x;
    const int bc0 = blockIdx.x * 64;
    const int k1  = 95 - blockIdx.y;        // big rings first
    const int m0  = blockIdx.z * 64;

    const int nlon  = 24 + 4 * k1;
    const int slon1 = 2 * k1 * k1 + 22 * k1;
    const int q2r   = k1 + 1;
    const int slon2 = NGRID - (2 * q2r * q2r + 22 * q2r);
    int mmax = 12 + 2 * k1;
    if (mmax > MDIM - 1) mmax = MDIM - 1;
    if (m0 > mmax) return;
    const int half = nlon >> 1;
    const int h2   = half >> 1;             // integer: nlon % 4 == 0
    const int ntiles = (h2 + 16) >> 4;      // ceil((h2+1)/16)

    const u32 sb = s2u(smA);
    const u32 XS = sb + 16384;

    // staging roles
    const int ppb = t >> 4, mq = (t & 15) * 4;   // basis: 1 q-row, 4 consecutive m
    const int bcr = t >> 1, pq = (t & 1) * 8;    // x: 1 (ring,bc)-row, 8 folded q
    const int ring = bcr >> 6, bcl = bcr & 63;

    // compute roles
    const int w = t >> 5, lane = t & 31;
    const int par = w & 1, mch = (w >> 1) & 1, bw = w >> 2;
    const int lm = lane >> 3, lb = lane & 7;

    const float* xrow  = x + (size_t)(bc0 + bcl) * NGRID + (ring ? slon2 : slon1);
    const float* cbase = cosb + ((size_t)k1 * PMAX) * MDIM + m0 + mq;
    const float* sbase = sinb + ((size_t)k1 * PMAX) * MDIM + m0 + mq;

    u64 acc0[4][4], acc1[4][4];
#pragma unroll
    for (int j = 0; j < 4; j++)
#pragma unroll
        for (int i = 0; i < 4; i++) { acc0[j][i] = 0ull; acc1[j][i] = 0ull; }

    float4 c4, s4, fw0, fw1, ba0, ba1;
    float2 e0, em2, em4, em6, em8, g0, g2, g4, g6;
    float ps;
    int p0s;
    const float4 z4 = make_float4(0.f, 0.f, 0.f, 0.f);
    const float2 z2 = make_float2(0.f, 0.f);

    auto prefetch = [&](int p0) {
        p0s = p0;
        int p = p0 + ppb;                   // basis q-row, p <= h2+15 < PMAX
        c4 = *(const float4*)(cbase + (size_t)p * MDIM);
        s4 = *(const float4*)(sbase + (size_t)p * MDIM);
        int q0 = p0 + pq;
        if (q0 <= h2) {
            fw0 = *(const float4*)(xrow + q0);
            fw1 = *(const float4*)(xrow + q0 + 4);
            ba0 = *(const float4*)(xrow + nlon - q0 - 4);
            ba1 = *(const float4*)(xrow + nlon - q0 - 8);
            ps  = (q0 >= 1) ? xrow[nlon - q0] : 0.f;
            int E = half - q0;
            e0  = *(const float2*)(xrow + E);
            em2 = *(const float2*)(xrow + E - 2);
            em4 = *(const float2*)(xrow + E - 4);
            em6 = *(const float2*)(xrow + E - 6);
            em8 = *(const float2*)(xrow + E - 8);
            g0  = *(const float2*)(xrow + half + q0);
            g2  = *(const float2*)(xrow + half + q0 + 2);
            g4  = *(const float2*)(xrow + half + q0 + 4);
            g6  = *(const float2*)(xrow + half + q0 + 6);
        } else {
            fw0 = fw1 = ba0 = ba1 = z4; ps = 0.f;
            e0 = em2 = em4 = em6 = em8 = g0 = g2 = g4 = g6 = z2;
        }
    };

    auto store_tile = [&](int buf) {
        // basis: parity-compacted; m = m0+mq+i, parity = i&1 (m0, mq even)
        u32 cs = sb + buf * 8192 + ppb * 512 + (mq >> 1) * 8;
        sts4(cs,       c4.x, s4.x, c4.z, s4.z);   // par 0: mc, mc+1
        sts4(cs + 256, c4.y, s4.y, c4.w, s4.w);   // par 1: mc, mc+1
        // x: four folded streams
        const float FA[8] = {fw0.x, fw0.y, fw0.z, fw0.w, fw1.x, fw1.y, fw1.z, fw1.w};
        const float PA[8] = {ps, ba0.w, ba0.z, ba0.y, ba0.x, ba1.w, ba1.z, ba1.y};
        const float HB[8] = {e0.x, em2.y, em2.x, em4.y, em4.x, em6.y, em6.x, em8.y};
        const float HP[8] = {g0.x, g0.y, g2.x, g2.y, g4.x, g4.y, g6.x, g6.y};
        u32 xa = XS + buf * 32768 + pq * 2048 + ring * 512 + bcl * 8;
        int q0 = p0s + pq;
#pragma unroll
        for (int i = 0; i < 8; i++) {
            int q = q0 + i;
            float XA, XB, XC, XD;
            if (q > h2) { XA = XB = XC = XD = 0.f; }
            else if (q == 0) {
                XA = FA[0] + HB[0]; XC = FA[0] - HB[0]; XB = 0.f; XD = 0.f;
            } else if (q == h2) {
                float xpa = FA[i] + PA[i], xma = FA[i] - PA[i];
                XA = xpa; XC = xpa; XB = xma; XD = xma;
            } else {
                float xpa = FA[i] + PA[i], xma = FA[i] - PA[i];
                float xpb = HB[i] + HP[i], xmb = HB[i] - HP[i];
                XA = xpa + xpb; XB = xma - xmb;
                XC = xpa - xpb; XD = xma + xmb;
            }
            sts2(xa + i * 2048,        XA, XB);   // even-m stream
            sts2(xa + i * 2048 + 1024, XC, XD);   // odd-m stream
        }
    };

    auto compute = [&](int buf) {
        u32 cs = sb + buf * 8192 + par * 256 + (mch * 16 + lm * 4) * 8;
        u32 xs = XS + buf * 32768 + par * 1024 + bw * 256 + lb * 16;
#pragma unroll
        for (int qq = 0; qq < 16; ++qq) {
            u64 b0, b1, b2, b3;
            lds2(b0, b1, cs + qq * 512);
            lds2(b2, b3, cs + qq * 512 + 16);
            u64 v0, v1, v2, v3, u0, u1, u2, u3;
            lds2(v0, v1, xs + qq * 2048);          // ring0 bc {2lb,2lb+1}
            lds2(v2, v3, xs + qq * 2048 + 128);    // ring0 bc +16
            lds2(u0, u1, xs + qq * 2048 + 512);    // ring1
            lds2(u2, u3, xs + qq * 2048 + 640);
            acc0[0][0] = ffma2(b0, v0, acc0[0][0]);
            acc0[0][1] = ffma2(b0, v1, acc0[0][1]);
            acc0[0][2] = ffma2(b0, v2, acc0[0][2]);
            acc0[0][3] = ffma2(b0, v3, acc0[0][3]);
            acc0[1][0] = ffma2(b1, v0, acc0[1][0]);
            acc0[1][1] = ffma2(b1, v1, acc0[1][1]);
            acc0[1][2] = ffma2(b1, v2, acc0[1][2]);
            acc0[1][3] = ffma2(b1, v3, acc0[1][3]);
            acc0[2][0] = ffma2(b2, v0, acc0[2][0]);
            acc0[2][1] = ffma2(b2, v1, acc0[2][1]);
            acc0[2][2] = ffma2(b2, v2, acc0[2][2]);
            acc0[2][3] = ffma2(b2, v3, acc0[2][3]);
            acc0[3][0] = ffma2(b3, v0, acc0[3][0]);
            acc0[3][1] = ffma2(b3, v1, acc0[3][1]);
            acc0[3][2] = ffma2(b3, v2, acc0[3][2]);
            acc0[3][3] = ffma2(b3, v3, acc0[3][3]);
            acc1[0][0] = ffma2(b0, u0, acc1[0][0]);
            acc1[0][1] = ffma2(b0, u1, acc1[0][1]);
            acc1[0][2] = ffma2(b0, u2, acc1[0][2]);
            acc1[0][3] = ffma2(b0, u3, acc1[0][3]);
            acc1[1][0] = ffma2(b1, u0, acc1[1][0]);
            acc1[1][1] = ffma2(b1, u1, acc1[1][1]);
            acc1[1][2] = ffma2(b1, u2, acc1[1][2]);
            acc1[1][3] = ffma2(b1, u3, acc1[1][3]);
            acc1[2][0] = ffma2(b2, u0, acc1[2][0]);
            acc1[2][1] = ffma2(b2, u1, acc1[2][1]);
            acc1[2][2] = ffma2(b2, u2, acc1[2][2]);
            acc1[2][3] = ffma2(b2, u3, acc1[2][3]);
            acc1[3][0] = ffma2(b3, u0, acc1[3][0]);
            acc1[3][1] = ffma2(b3, u1, acc1[3][1]);
            acc1[3][2] = ffma2(b3, u2, acc1[3][2]);
            acc1[3][3] = ffma2(b3, u3, acc1[3][3]);
        }
    };

    prefetch(0);
    store_tile(0);
    __syncthreads();
    for (int ti = 0; ti < ntiles; ++ti) {
        bool nx = (ti + 1) < ntiles;
        if (nx) prefetch((ti + 1) << 4);
        compute(ti & 1);
        if (nx) store_tile((ti + 1) & 1);
        __syncthreads();
    }

    // epilogue: hemisphere fold (ring pair), scale 2*pi, STG.128.
    // m = m0 + 2*(mch*16 + lm*4 + j) + par; bc = bc0 + bw*32 + 2lb {+0,+1,+16,+17}
    const u64 tp2  = pk2(TWO_PI_F, TWO_PI_F);
    const u64 NEG1 = pk2(-1.f, -1.f);
#pragma unroll
    for (int j = 0; j < 4; j++) {
        int m = m0 + 2 * (mch * 16 + lm * 4 + j) + par;
        size_t base = ((size_t)m * KF + k1) * BCN + bc0 + bw * 32 + 2 * lb;
        u64* op = g_rip + base;
        u64* om = g_rim + base;
        ulonglong2 wp0, wp1, wm0, wm1;
        wp0.x = fmul2(fadd2(acc0[j][0], acc1[j][0]), tp2);
        wp0.y = fmul2(fadd2(acc0[j][1], acc1[j][1]), tp2);
        wp1.x = fmul2(fadd2(acc0[j][2], acc1[j][2]), tp2);
        wp1.y = fmul2(fadd2(acc0[j][3], acc1[j][3]), tp2);
        wm0.x = fmul2(ffma2(acc1[j][0], NEG1, acc0[j][0]), tp2);
        wm0.y = fmul2(ffma2(acc1[j][1], NEG1, acc0[j][1]), tp2);
        wm1.x = fmul2(ffma2(acc1[j][2], NEG1, acc0[j][2]), tp2);
        wm1.y = fmul2(ffma2(acc1[j][3], NEG1, acc0[j][3]), tp2);
        *(ulonglong2*)op        = wp0;
        *(ulonglong2*)(op + 16) = wp1;
        *(ulonglong2*)om        = wm0;
        *(ulonglong2*)(om + 16) = wm1;
    }
}

// ---------------------------------------------------------------------------
// Stage B: per-m GEMM on pre-folded operands, parity-coherent warps.
//   st[m,l,bc] = sum_{k in [klo,95]} W[m,l,k] * ( (l+m) even ? A+[k] : A-[k] )
// grid = (16 bc-tiles of 64, 3 l-tiles of 64, 192 m), block = 128.
// ---------------------------------------------------------------------------
extern "C" __global__ void __launch_bounds__(128, 4)
sht_stageB(const float* __restrict__ weight)
{
    __shared__ __align__(16) unsigned char sm[4 * 16 * 512 + 2 * 16 * 256];  // 40960
    const int t   = threadIdx.x;
    const int bc0 = blockIdx.x * 64;
    const int l0  = blockIdx.y * 64;
    const int m   = blockIdx.z;
    if (l0 + 63 < m) return;                // zero triangle: handled by transpose

    const int klo = (m <= 12) ? 0 : ((m - 11) >> 1);
    const int kb0 = klo & ~15;
    const int nkt = ((95 - kb0) >> 4) + 1;

    const u32 sb  = s2u(sm);
    const u32 APS = sb;
    const u32 AMS = sb + 16384;
    const u32 WS  = sb + 32768;

    const int lr = t >> 1, kq = (t & 1) * 8;
    const int wpar = (lr + m) & 1, wlc = lr >> 1;

    const int w = t >> 5, lane = t & 31;
    const int pw  = w & 1;
    const int h   = w >> 1;
    const int lc0 = (lane >> 3) * 8;
    const int bto = h * 32 + (lane & 7) * 4;
    const int dlt = pw ^ (m & 1);

    const float* wrow   = weight + ((size_t)m * MDIM + l0 + lr) * KR;
    const u64*   apbase = g_rip + ((size_t)m * KF) * BCN + bc0;
    const u64*   ambase = g_rim + ((size_t)m * KF) * BCN + bc0;

    u64 acc[8][4];
#pragma unroll
    for (int j = 0; j < 8; j++)
#pragma unroll
        for (int i = 0; i < 4; i++) acc[j][i] = 0ull;

    float4 w40, w41;
    auto cpa_tile = [&](int buf, int kb) {
#pragma unroll
        for (int c = 0; c < 4; c++) {
            int chunk = t * 4 + c;
            int kk = chunk >> 5, col = chunk & 31;
            int kg = kb + kk;
            int bytes = (kg >= klo) ? 16 : 0;
            cpa16(APS + buf * 8192 + kk * 512 + col * 16,
                  apbase + (size_t)kg * BCN + col * 2, bytes);
            cpa16(AMS + buf * 8192 + kk * 512 + col * 16,
                  ambase + (size_t)kg * BCN + col * 2, bytes);
        }
        cpcommit();
    };
    auto ldW = [&](int kb) {
        w40 = *(const float4*)(wrow + kb + kq);
        w41 = *(const float4*)(wrow + kb + kq + 4);
    };
    auto stW = [&](int buf) {
        u32 ws = WS + buf * 4096 + wpar * 128 + wlc * 4;
        sts1(ws + (kq + 0) * 256, w40.x);
        sts1(ws + (kq + 1) * 256, w40.y);
        sts1(ws + (kq + 2) * 256, w40.z);
        sts1(ws + (kq + 3) * 256, w40.w);
        sts1(ws + (kq + 4) * 256, w41.x);
        sts1(ws + (kq + 5) * 256, w41.y);
        sts1(ws + (kq + 6) * 256, w41.z);
        sts1(ws + (kq + 7) * 256, w41.w);
    };

    const u32 AT = pw ? AMS : APS;

    auto compute = [&](int buf) {
        u32 as_ = AT + buf * 8192 + bto * 8;
        u32 ws  = WS + buf * 4096 + pw * 128 + lc0 * 4;
#pragma unroll
        for (int kk = 0; kk < 16; ++kk) {
            u64 a[4];
            lds2(a[0], a[1], as_ + kk * 512);
            lds2(a[2], a[3], as_ + kk * 512 + 16);
            float4 f0 = lds4f(ws + kk * 256);
            float4 f1 = lds4f(ws + kk * 256 + 16);
            const float fw[8] = {f0.x, f0.y, f0.z, f0.w, f1.x, f1.y, f1.z, f1.w};
#pragma unroll
            for (int j = 0; j < 8; j++) {
                u64 ww = pk2(fw[j], fw[j]);
#pragma unroll
                for (int i = 0; i < 4; i++)
                    acc[j][i] = ffma2(a[i], ww, acc[j][i]);
            }
        }
    };

    cpa_tile(0, kb0);
    ldW(kb0);
    stW(0);
    cpwait0();
    __syncthreads();
    for (int ti = 0; ti < nkt; ++ti) {
        int kb = kb0 + ((ti + 1) << 4);
        bool nx = (ti + 1) < nkt;
        if (nx) { cpa_tile((ti + 1) & 1, kb); ldW(kb); }
        compute(ti & 1);
        if (nx) { stW((ti + 1) & 1); cpwait0(); }
        __syncthreads();
    }

#pragma unroll
    for (int j = 0; j < 8; j++) {
        int l = l0 + 2 * (lc0 + j) + dlt;
        u64* o = g_st + (((size_t)m * MDIM) + l) * BCN + bc0 + bto;
        ulonglong2 w0, w1;
        w0.x = acc[j][0]; w0.y = acc[j][1];
        w1.x = acc[j][2]; w1.y = acc[j][3];
        *(ulonglong2*)o       = w0;
        *(ulonglong2*)(o + 2) = w1;
    }
}

// ---------------------------------------------------------------------------
// Transpose: out[bc][l][m] <- g_st[m][l][bc]; zero for l < m.
// ---------------------------------------------------------------------------
extern "C" __global__ void __launch_bounds__(256)
sht_transpose(u64* __restrict__ out)
{
    __shared__ u64 smt[32][65];
    const int t   = threadIdx.x;
    const int bc0 = blockIdx.x * 64;
    const int m0  = blockIdx.y * 32;
    const int l   = blockIdx.z;

    const int mr  = t >> 5;
    const int bcc = (t & 31) * 2;
#pragma unroll
    for (int r = 0; r < 4; ++r) {
        int ml = mr + r * 8;
        ulonglong2 v;
        if (l >= m0 + ml)
            v = *(const ulonglong2*)(g_st + (((size_t)(m0 + ml)) * MDIM + l) * BCN + bc0 + bcc);
        else
            v = make_ulonglong2(0ull, 0ull);
        smt[ml][bcc]     = v.x;
        smt[ml][bcc + 1] = v.y;
    }
    __syncthreads();

    const int bcr = t >> 4;
    const int mc  = (t & 15) * 2;
#pragma unroll
    for (int r = 0; r < 4; ++r) {
        int bcl = bcr + r * 16;
        ulonglong2 v;
        v.x = smt[mc][bcl];
        v.y = smt[mc + 1][bcl];
        *(ulonglong2*)(out + (((size_t)(bc0 + bcl)) * MDIM + l) * MDIM + m0 + mc) = v;
    }
}

// ---------------------------------------------------------------------------

extern "C" void kernel_launch(void* const* d_in, const int* in_sizes, int n_in,
                              void* d_out, int out_size)
{
    (void)in_sizes; (void)n_in; (void)out_size;
    const float* x      = (const float*)d_in[0];
    const float* weight = (const float*)d_in[1];
    const float* cosb   = (const float*)d_in[2];
    const float* sinb   = (const float*)d_in[3];

    const int smemA = 81920;
    cudaFuncSetAttribute(sht_stageA, cudaFuncAttributeMaxDynamicSharedMemorySize, smemA);

    dim3 gA(16, 96, 3);
    sht_stageA<<<gA, 256, smemA>>>(x, cosb, sinb);

    dim3 gB(16, 3, 192);
    sht_stageB<<<gB, 128>>>(weight);

    dim3 gT(16, 6, 192);
    sht_transpose<<<gT, 256>>>((u64*)d_out);
}